// round 14
// baseline (speedup 1.0000x reference)
#include <cuda_runtime.h>
#include <cstdint>

// TaylorExp: out row (273) = [1, x*0.5 (16), outer(sx,sx) (256)]
// sx = x * sqrt(1/(sqrt(2)*sqrt(16)))
//
// Round-14: 3 chunks x 3 dedicated smem buffers per CTA, ZERO reuse gates
// (R10's regression came from wait_group-1 gates, not depth). Stores issued
// back-to-back as each chunk completes; single wait_group 0 at exit.
// All 3 inputs prefetched at entry (MLP=3). evict_first on all bulk stores.

#define QUAD_SQRT_SCALE 0.42044820762685725f
#define T1_SCALE        0.5f
#define ROWS_PER_CHUNK  4
#define CHUNKS_PER_CTA  3
#define THREADS         128
#define ROW_LEN         273
#define CHUNK_FLOATS    (ROWS_PER_CHUNK * ROW_LEN)   // 1092
#define CHUNK_BYTES     (CHUNK_FLOATS * 4)           // 4368 = 273*16

__device__ __forceinline__ void compute_chunk_from_val(
    float xv, float* __restrict__ sbuf, int warp, int lane)
{
    float* __restrict__ srow = sbuf + warp * ROW_LEN;

    if (lane < 16)  srow[1 + lane] = xv * T1_SCALE;
    if (lane == 16) srow[0] = 1.0f;

    float sx = xv * QUAD_SQRT_SCALE;
    #pragma unroll
    for (int k = 0; k < 8; k++) {
        int q = lane + 32 * k;                       // 0..255
        float vr = __shfl_sync(0xffffffffu, sx, q >> 4);
        float vc = __shfl_sync(0xffffffffu, sx, q & 15);
        srow[17 + q] = vr * vc;
    }
}

__device__ __forceinline__ void issue_store(
    float* __restrict__ out, const float* __restrict__ sbuf, int chunk)
{
    uint32_t saddr = (uint32_t)__cvta_generic_to_shared(sbuf);
    float* gdst = out + (size_t)chunk * CHUNK_FLOATS;
    asm volatile("fence.proxy.async.shared::cta;" ::: "memory");
    asm volatile(
        "{\n\t"
        ".reg .b64 pol;\n\t"
        "createpolicy.fractional.L2::evict_first.b64 pol, 1.0;\n\t"
        "cp.async.bulk.global.shared::cta.bulk_group.L2::cache_hint"
        " [%0], [%1], %2, pol;\n\t"
        "}"
        :: "l"(gdst), "r"(saddr), "r"((uint32_t)CHUNK_BYTES)
        : "memory");
    asm volatile("cp.async.bulk.commit_group;" ::: "memory");
}

__global__ void __launch_bounds__(THREADS) taylor_exp_kernel(
    const float* __restrict__ x,
    float* __restrict__ out,
    int rows)
{
    __shared__ __align__(16) float s[CHUNKS_PER_CTA][CHUNK_FLOATS];

    const int warp = threadIdx.x >> 5;
    const int lane = threadIdx.x & 31;
    const int cbase = blockIdx.x * CHUNKS_PER_CTA;

    // prefetch ALL chunks' inputs (independent loads, MLP=3)
    float xv[CHUNKS_PER_CTA];
    #pragma unroll
    for (int c = 0; c < CHUNKS_PER_CTA; c++) {
        const int row = (cbase + c) * ROWS_PER_CHUNK + warp;
        xv[c] = (lane < 16 && row < rows) ? x[(size_t)row * 16 + lane] : 0.0f;
    }

    bool issued = false;

    #pragma unroll
    for (int c = 0; c < CHUNKS_PER_CTA; c++) {
        const int chunk = cbase + c;
        const int valid = min(ROWS_PER_CHUNK, rows - chunk * ROWS_PER_CHUNK);
        if (valid <= 0) break;

        const int row = chunk * ROWS_PER_CHUNK + warp;
        if (row < rows) compute_chunk_from_val(xv[c], s[c], warp, lane);
        __syncthreads();

        if (valid == ROWS_PER_CHUNK) {
            if (threadIdx.x == 0) issue_store(out, s[c], chunk);
            issued = true;
        } else {
            // tail chunk: scalar bounds-checked flush
            const size_t base = (size_t)chunk * CHUNK_FLOATS;
            const int nfloats = valid * ROW_LEN;
            for (int i = threadIdx.x; i < nfloats; i += THREADS)
                out[base + i] = s[c][i];
        }
    }

    // single drain-wait for all bulk stores (smem safety before CTA exit)
    if (issued && threadIdx.x == 0)
        asm volatile("cp.async.bulk.wait_group 0;" ::: "memory");
}

extern "C" void kernel_launch(void* const* d_in, const int* in_sizes, int n_in,
                              void* d_out, int out_size)
{
    const float* x = (const float*)d_in[0];
    float* out = (float*)d_out;

    int rows = in_sizes[0] / 16;
    int rows_per_cta = ROWS_PER_CHUNK * CHUNKS_PER_CTA;       // 12
    int blocks = (rows + rows_per_cta - 1) / rows_per_cta;

    taylor_exp_kernel<<<blocks, THREADS>>>(x, out, rows);
}